// round 1
// baseline (speedup 1.0000x reference)
#include <cuda_runtime.h>
#include <math.h>

#define B_   32
#define S_   64
#define E_   512
#define H_   1024
#define V_   32000
#define G3H  (3 * H_)
#define NTOK (B_ * S_)
#define BH   (B_ * H_)

// ---------------- scratch (device globals; no allocation allowed) ----------------
__device__ float g_ex[NTOK * E_];     // encoder embeddings  [2048, 512]
__device__ float g_dx[NTOK * E_];     // decoder embeddings  [2048, 512]
__device__ float g_xg[NTOK * G3H];    // precomputed input gates [2048, 3072] (reused per layer)
__device__ float g_seqA[NTOK * H_];   // sequence buffer (y0 / d0)
__device__ float g_seqB[NTOK * H_];   // sequence buffer (d1)
__device__ float g_h[8][BH];          // 4 layers x ping-pong hidden state [32,1024]

// ---------------- embedding gather ----------------
__global__ void embed_kernel(const int* __restrict__ idx,
                             const float* __restrict__ emb,
                             float* __restrict__ out) {
    int tok = blockIdx.x;
    int row = idx[tok];
    const float4* src = (const float4*)(emb + (size_t)row * E_);
    float4* dst = (float4*)(out + (size_t)tok * E_);
    for (int i = threadIdx.x; i < E_ / 4; i += blockDim.x) dst[i] = src[i];
}

// ---------------- fp32 SGEMM: C[M,N] = A[M,K] * W[N,K]^T + bias[N] ----------------
// Both operands K-major. 128x128 tile, BK=8, 256 threads, 8x8 per thread.
// Requires M%128==0, N%128==0, K%8==0 (true for all uses here).
#define BM 128
#define BN 128
#define BK 8

__global__ __launch_bounds__(256)
void sgemm_bias_kernel(const float* __restrict__ A,
                       const float* __restrict__ W,
                       const float* __restrict__ bias,
                       float* __restrict__ C,
                       int M, int N, int K) {
    __shared__ float As[BK][BM];
    __shared__ float Bs[BK][BN];

    const int tid = threadIdx.x;
    const int bm = blockIdx.y * BM;
    const int bn = blockIdx.x * BN;

    const int lr = tid >> 1;          // 0..127 : row within tile
    const int lk = (tid & 1) * 4;     // 0 or 4 : k quad

    const int tx = tid & 15;          // 0..15
    const int ty = tid >> 4;          // 0..15

    float acc[8][8];
#pragma unroll
    for (int i = 0; i < 8; i++)
#pragma unroll
        for (int j = 0; j < 8; j++) acc[i][j] = 0.f;

    const float* Aptr = A + (size_t)(bm + lr) * K + lk;
    const float* Wptr = W + (size_t)(bn + lr) * K + lk;

    for (int k0 = 0; k0 < K; k0 += BK) {
        float4 av = *(const float4*)(Aptr + k0);
        float4 bv = *(const float4*)(Wptr + k0);
        As[lk + 0][lr] = av.x; As[lk + 1][lr] = av.y;
        As[lk + 2][lr] = av.z; As[lk + 3][lr] = av.w;
        Bs[lk + 0][lr] = bv.x; Bs[lk + 1][lr] = bv.y;
        Bs[lk + 2][lr] = bv.z; Bs[lk + 3][lr] = bv.w;
        __syncthreads();

#pragma unroll
        for (int k = 0; k < BK; k++) {
            float a[8], b[8];
            *(float4*)&a[0] = *(const float4*)&As[k][ty * 4];
            *(float4*)&a[4] = *(const float4*)&As[k][64 + ty * 4];
            *(float4*)&b[0] = *(const float4*)&Bs[k][tx * 4];
            *(float4*)&b[4] = *(const float4*)&Bs[k][64 + tx * 4];
#pragma unroll
            for (int i = 0; i < 8; i++)
#pragma unroll
                for (int j = 0; j < 8; j++) acc[i][j] += a[i] * b[j];
        }
        __syncthreads();
    }

    // epilogue: bias add + vectorized stores
#pragma unroll
    for (int i = 0; i < 8; i++) {
        int m = bm + ((i < 4) ? (ty * 4 + i) : (64 + ty * 4 + (i - 4)));
#pragma unroll
        for (int half = 0; half < 2; half++) {
            int n = bn + half * 64 + tx * 4;
            float4 bv = *(const float4*)(bias + n);
            float4 o;
            o.x = acc[i][half * 4 + 0] + bv.x;
            o.y = acc[i][half * 4 + 1] + bv.y;
            o.z = acc[i][half * 4 + 2] + bv.z;
            o.w = acc[i][half * 4 + 3] + bv.w;
            *(float4*)(C + (size_t)m * N + n) = o;
        }
    }
}

// ---------------- fused GRU time step ----------------
// h_new[b,j] from h_prev[32,1024], Whh[3H,H], bhh[3H], xg[B,S,3H] (precomputed + bih).
// grid: 128 blocks (8 j's each), 256 threads = 32 batches x 8 j-warps.
// h held in smem transposed [k][b] -> conflict-free; weights per-warp uniform (L2 broadcast).
__global__ __launch_bounds__(256)
void gru_step_kernel(const float* __restrict__ h_prev,
                     const float* __restrict__ Whh,
                     const float* __restrict__ bhh,
                     const float* __restrict__ xg,
                     int t, int zero_init,
                     float* __restrict__ h_next,
                     float* __restrict__ y) {
    extern __shared__ float h_s[];   // [H_][B_] = 1024 x 32 floats = 128 KB

    const int tid = threadIdx.x;
    const int b = tid & 31;
    const int j = (blockIdx.x << 3) + (tid >> 5);

    float accr = bhh[j];
    float accz = bhh[H_ + j];
    float accn = bhh[2 * H_ + j];
    float h_old = 0.f;

    if (!zero_init) {
        // cooperative transpose-load of h into smem
        for (int i4 = tid; i4 < BH / 4; i4 += 256) {
            int lin = i4 * 4;
            int bb = lin >> 10;            // /H_
            int kk = lin & (H_ - 1);
            float4 v = *(const float4*)(h_prev + lin);
            h_s[(kk + 0) * B_ + bb] = v.x;
            h_s[(kk + 1) * B_ + bb] = v.y;
            h_s[(kk + 2) * B_ + bb] = v.z;
            h_s[(kk + 3) * B_ + bb] = v.w;
        }
        __syncthreads();

        const float* wr = Whh + (size_t)j * H_;
        const float* wz = Whh + (size_t)(H_ + j) * H_;
        const float* wn = Whh + (size_t)(2 * H_ + j) * H_;

#pragma unroll 4
        for (int k = 0; k < H_; k += 4) {
            float4 r4 = *(const float4*)(wr + k);
            float4 z4 = *(const float4*)(wz + k);
            float4 n4 = *(const float4*)(wn + k);
            float h0 = h_s[(k + 0) * B_ + b];
            float h1 = h_s[(k + 1) * B_ + b];
            float h2 = h_s[(k + 2) * B_ + b];
            float h3 = h_s[(k + 3) * B_ + b];
            accr += h0 * r4.x + h1 * r4.y + h2 * r4.z + h3 * r4.w;
            accz += h0 * z4.x + h1 * z4.y + h2 * z4.z + h3 * z4.w;
            accn += h0 * n4.x + h1 * n4.y + h2 * n4.z + h3 * n4.w;
        }
        h_old = h_s[j * B_ + b];
    }

    const float* xp = xg + ((size_t)b * S_ + t) * G3H;
    float r = 1.f / (1.f + expf(-(xp[j] + accr)));
    float z = 1.f / (1.f + expf(-(xp[H_ + j] + accz)));
    float n = tanhf(xp[2 * H_ + j] + r * accn);
    float hnew = (1.f - z) * n + z * h_old;

    h_next[b * H_ + j] = hnew;
    if (y) y[((size_t)b * S_ + t) * H_ + j] = hnew;
}

// ---------------- driver ----------------
static void run_scan(const float* Whh, const float* bhh, const float* xg,
                     float* hpair, const float* h_init, int zero0, float* yout) {
    for (int t = 0; t < S_; t++) {
        const float* hin;
        int zi = 0;
        if (t == 0) {
            if (zero0) { hin = hpair; zi = 1; }  // hin unused when zi=1
            else       { hin = h_init; }
        } else {
            hin = hpair + (t & 1) * BH;
        }
        float* hout = hpair + ((t + 1) & 1) * BH;
        gru_step_kernel<<<128, 256, 131072>>>(hin, Whh, bhh, xg, t, zi, hout, yout);
    }
}

extern "C" void kernel_launch(void* const* d_in, const int* in_sizes, int n_in,
                              void* d_out, int out_size) {
    const int*   enc_X   = (const int*)d_in[0];
    const int*   dec_X   = (const int*)d_in[1];
    const float* emb_enc = (const float*)d_in[2];
    const float* emb_dec = (const float*)d_in[3];
    const float* eW0i = (const float*)d_in[4];
    const float* eW0h = (const float*)d_in[5];
    const float* eb0i = (const float*)d_in[6];
    const float* eb0h = (const float*)d_in[7];
    const float* eW1i = (const float*)d_in[8];
    const float* eW1h = (const float*)d_in[9];
    const float* eb1i = (const float*)d_in[10];
    const float* eb1h = (const float*)d_in[11];
    const float* dW0i = (const float*)d_in[12];
    const float* dW0h = (const float*)d_in[13];
    const float* db0i = (const float*)d_in[14];
    const float* db0h = (const float*)d_in[15];
    const float* dW1i = (const float*)d_in[16];
    const float* dW1h = (const float*)d_in[17];
    const float* db1i = (const float*)d_in[18];
    const float* db1h = (const float*)d_in[19];
    const float* fcW  = (const float*)d_in[20];
    const float* fcb  = (const float*)d_in[21];
    float* out = (float*)d_out;

    float *ex, *dx, *xg, *seqA, *seqB, *hb;
    cudaGetSymbolAddress((void**)&ex,   g_ex);
    cudaGetSymbolAddress((void**)&dx,   g_dx);
    cudaGetSymbolAddress((void**)&xg,   g_xg);
    cudaGetSymbolAddress((void**)&seqA, g_seqA);
    cudaGetSymbolAddress((void**)&seqB, g_seqB);
    cudaGetSymbolAddress((void**)&hb,   g_h);

    cudaFuncSetAttribute(gru_step_kernel,
                         cudaFuncAttributeMaxDynamicSharedMemorySize, 131072);

    // embeddings
    embed_kernel<<<NTOK, 128>>>(enc_X, emb_enc, ex);
    embed_kernel<<<NTOK, 128>>>(dec_X, emb_dec, dx);

    dim3 gemm_grid_3h(G3H / BN, NTOK / BM);

    // encoder layer 0
    sgemm_bias_kernel<<<gemm_grid_3h, 256>>>(ex, eW0i, eb0i, xg, NTOK, G3H, E_);
    run_scan(eW0h, eb0h, xg, hb + 0 * 2 * BH, nullptr, 1, seqA);   // y0 -> seqA, final h @ pair0 buf0

    // encoder layer 1 (sequence output unused; only final hidden needed)
    sgemm_bias_kernel<<<gemm_grid_3h, 256>>>(seqA, eW1i, eb1i, xg, NTOK, G3H, H_);
    run_scan(eW1h, eb1h, xg, hb + 1 * 2 * BH, nullptr, 1, nullptr); // final h @ pair1 buf0

    // decoder layer 0 (init = enc layer0 final hidden)
    sgemm_bias_kernel<<<gemm_grid_3h, 256>>>(dx, dW0i, db0i, xg, NTOK, G3H, E_);
    run_scan(dW0h, db0h, xg, hb + 2 * 2 * BH, hb + 0 * 2 * BH, 0, seqA); // d0 -> seqA

    // decoder layer 1 (init = enc layer1 final hidden)
    sgemm_bias_kernel<<<gemm_grid_3h, 256>>>(seqA, dW1i, db1i, xg, NTOK, G3H, H_);
    run_scan(dW1h, db1h, xg, hb + 3 * 2 * BH, hb + 1 * 2 * BH, 0, seqB); // d1 -> seqB

    // final projection to vocab
    dim3 fc_grid(V_ / BN, NTOK / BM);
    sgemm_bias_kernel<<<fc_grid, 256>>>(seqB, fcW, fcb, out, NTOK, V_, H_);
}